// round 12
// baseline (speedup 1.0000x reference)
#include <cuda_runtime.h>
#include <cuda_fp16.h>
#include <cstdint>

// out[b,h,o] = sum_{i,d} x[b,h,i,d] * ws[o,i] * weight[o,d]
// => C (8192x1024) = A (8192x4096 fp32 = x) . W2^T,  W2[n,k]=ws[n,k>>2]*weight[n,k&3]
// Single-term fp16 HMMA GEMM, R9 shape (2x2 warp grid, 64x64 warp tiles, BK=32,
// 4 stages). This round: convert_x deleted -- A converts fp32->fp16 inside the
// GEMM on the register path, in two 4-chunk waves whose LDG latency is buried
// under the ks0 / ks1 mma blocks (16 transient regs; crossbar budget unchanged).

#define M_DIM 8192
#define N_DIM 1024
#define K_DIM 4096
#define BM 128
#define BN 128
#define BK 32
#define KT (K_DIM / BK)        // 128
#define ROWB 80                // 32 f16 (64B) + 16B pad -> conflict-free ldmatrix
#define TILE_B (128 * ROWB)    // 10240 B per tile
#define STAGE (2 * TILE_B)     // A tile + B tile = 20480 B
#define NSTAGE 4
#define SMEM_BYTES (NSTAGE * STAGE)   // 81920 B -> 2 CTAs/SM

// Precomputed fp16 W2 (row-major [N][K]).
__device__ __half g_b[(size_t)N_DIM * K_DIM];

// ---------------------------------------------------------------- helpers
__device__ __forceinline__ void ldsm_x4(uint32_t* r, uint32_t addr) {
    asm volatile("ldmatrix.sync.aligned.m8n8.x4.shared.b16 {%0,%1,%2,%3}, [%4];"
                 : "=r"(r[0]), "=r"(r[1]), "=r"(r[2]), "=r"(r[3]) : "r"(addr));
}
__device__ __forceinline__ void mma16816(float* c, const uint32_t* a, const uint32_t* b) {
    asm volatile(
        "mma.sync.aligned.m16n8k16.row.col.f32.f16.f16.f32 "
        "{%0,%1,%2,%3}, {%4,%5,%6,%7}, {%8,%9}, {%0,%1,%2,%3};"
        : "+f"(c[0]), "+f"(c[1]), "+f"(c[2]), "+f"(c[3])
        : "r"(a[0]), "r"(a[1]), "r"(a[2]), "r"(a[3]), "r"(b[0]), "r"(b[1]));
}
__device__ __forceinline__ void cp16(uint32_t dst, const void* src) {
    asm volatile("cp.async.cg.shared.global [%0], [%1], 16;"
                 :: "r"(dst), "l"(src) : "memory");
}
__device__ __forceinline__ uint32_t pack_h2(float a, float b) {
    uint32_t r;
    asm volatile("cvt.rn.f16x2.f32 %0, %1, %2;" : "=r"(r) : "f"(b), "f"(a));
    return r;
}
__device__ __forceinline__ void sts64(uint32_t addr, uint32_t a, uint32_t b) {
    asm volatile("st.shared.v2.u32 [%0], {%1,%2};" :: "r"(addr), "r"(a), "r"(b) : "memory");
}

// --------------------------------------- build W2 -> fp16 plane (~3us)
__global__ __launch_bounds__(256) void convert_w(const float* __restrict__ weight,
                                                 const float* __restrict__ ws) {
    size_t idx = (size_t)blockIdx.x * 256 + threadIdx.x;   // 524,288 threads
    int n  = (int)(idx >> 9);
    int kk = ((int)idx & 511) * 8;     // 8 consecutive k = 2 i-values x 4 d
    int i0 = kk >> 2;
    float2 sv = *(const float2*)(ws + (size_t)n * 1024 + i0);
    float4 wv = *(const float4*)(weight + n * 4);
    uint4 o;
    o.x = pack_h2(sv.x * wv.x, sv.x * wv.y);
    o.y = pack_h2(sv.x * wv.z, sv.x * wv.w);
    o.z = pack_h2(sv.y * wv.x, sv.y * wv.y);
    o.w = pack_h2(sv.y * wv.z, sv.y * wv.w);
    *(uint4*)(g_b + (size_t)n * K_DIM + kk) = o;
}

// ----------------------------------------------------------- fused HMMA GEMM
__global__ __launch_bounds__(128, 2)
void gemm_mma(const float* __restrict__ X, float* __restrict__ out) {
    extern __shared__ uint8_t smem[];
    uint32_t sbase = (uint32_t)__cvta_generic_to_shared(smem);

    const int tid = threadIdx.x, lane = tid & 31, wid = tid >> 5;
    const int wm = wid >> 1;          // 0..1  (64 rows)
    const int wn = wid & 1;           // 0..1  (64 cols)
    const int nt = blockIdx.x, mt = blockIdx.y;

    float c[4][8][4];
#pragma unroll
    for (int i = 0; i < 4; i++)
#pragma unroll
        for (int j = 0; j < 8; j++)
#pragma unroll
            for (int q = 0; q < 4; q++) c[i][j][q] = 0.0f;

    // A fp32 conversion addressing: lanes 0..7 cover one 128B row segment.
    const int arow = tid >> 3;        // 0..15
    const int ach  = tid & 7;         // 16B chunk in row -> 8B f16
    const float* asrc32 = X + ((size_t)(mt * BM) + arow) * K_DIM + ach * 4;
    const __half* bsrc = g_b + (size_t)nt * BN * K_DIM;

    // Load wave w (rows arow + w*64 + {0,16,32,48}) of stage kt's A tile.
    auto lda4 = [&](int kt, int w, float4* v) {
        const float* p = asrc32 + kt * BK + (size_t)(w * 64) * K_DIM;
#pragma unroll
        for (int it = 0; it < 4; it++)
            v[it] = *(const float4*)(p + (size_t)(it * 16) * K_DIM);
    };
    // Convert + store wave w into the fp16 A tile of stage kt.
    auto sta4 = [&](int kt, int w, const float4* v) {
        uint32_t sst = sbase + (kt % NSTAGE) * STAGE;
#pragma unroll
        for (int it = 0; it < 4; it++) {
            uint32_t dst = sst + (uint32_t)(arow + w * 64 + it * 16) * ROWB + ach * 8;
            sts64(dst, pack_h2(v[it].x, v[it].y), pack_h2(v[it].z, v[it].w));
        }
    };
    // B tile via cp.async: 4 chunks of 16B per thread.
    auto issue_b = [&](int kt) {
        int k0 = kt * BK;
        uint32_t sst = sbase + (kt % NSTAGE) * STAGE + TILE_B;
#pragma unroll
        for (int it = 0; it < 4; it++) {
            int idx = it * 128 + tid;          // 0..511
            int row = idx >> 2, ch = idx & 3;
            cp16(sst + row * ROWB + ch * 16,
                 bsrc + (size_t)row * K_DIM + k0 + ch * 8);
        }
    };

    // fragment smem addressing (constant per thread)
    const int rA = wm * 64 + (lane & 15);                          // + mf*16
    const uint32_t kAofs = (((uint32_t)lane >> 4) & 1) * 8;        // + ks*16
    const int rB = wn * 64 + (lane & 7) + (((lane >> 4) & 1) * 8); // + nh*16
    const uint32_t kBofs = (((uint32_t)lane >> 3) & 1) * 8;

    // prologue: A tiles for stages 0,1 via reg path; B stages 0..2 via cp.async
    {
        float4 v[4];
        lda4(0, 0, v); sta4(0, 0, v);
        lda4(0, 1, v); sta4(0, 1, v);
        lda4(1, 0, v); sta4(1, 0, v);
        lda4(1, 1, v); sta4(1, 1, v);
    }
    issue_b(0); asm volatile("cp.async.commit_group;" ::: "memory");
    issue_b(1); asm volatile("cp.async.commit_group;" ::: "memory");
    issue_b(2); asm volatile("cp.async.commit_group;" ::: "memory");

    for (int kt = 0; kt < KT; kt++) {
        asm volatile("cp.async.wait_group 2;" ::: "memory");
        __syncthreads();

        const bool pre = (kt + 2 < KT);
        float4 va[4];
        // LDG wave 0 for stage kt+2: issued now, consumed after ks0 mmas.
        if (pre) lda4(kt + 2, 0, va);
        // B refill for stage kt+3 (== kt-1 mod 4; safe after the barrier).
        if (kt + 3 < KT) issue_b(kt + 3);
        asm volatile("cp.async.commit_group;" ::: "memory");

        uint32_t sA = sbase + (kt % NSTAGE) * STAGE;
        uint32_t sB = sA + TILE_B;

        // ---- ks = 0 ----
        {
            uint32_t ka = kAofs * 2;
            uint32_t kb = kBofs * 2;
            uint32_t ah[4][4], bh[4][4];
#pragma unroll
            for (int nh = 0; nh < 4; nh++)
                ldsm_x4(bh[nh], sB + (uint32_t)(rB + nh * 16) * ROWB + kb);
#pragma unroll
            for (int mf = 0; mf < 4; mf++)
                ldsm_x4(ah[mf], sA + (uint32_t)(rA + mf * 16) * ROWB + ka);
#pragma unroll
            for (int mf = 0; mf < 4; mf++)
#pragma unroll
                for (int nf = 0; nf < 8; nf++)
                    mma16816(c[mf][nf], ah[mf], &bh[nf >> 1][(nf & 1) * 2]);
        }

        // store wave 0 (LDG long done), issue LDG wave 1 for stage kt+2
        if (pre) {
            sta4(kt + 2, 0, va);
            lda4(kt + 2, 1, va);
        }

        // ---- ks = 1 ----
        {
            uint32_t ka = (16 + kAofs) * 2;
            uint32_t kb = (16 + kBofs) * 2;
            uint32_t ah[4][4], bh[4][4];
#pragma unroll
            for (int nh = 0; nh < 4; nh++)
                ldsm_x4(bh[nh], sB + (uint32_t)(rB + nh * 16) * ROWB + kb);
#pragma unroll
            for (int mf = 0; mf < 4; mf++)
                ldsm_x4(ah[mf], sA + (uint32_t)(rA + mf * 16) * ROWB + ka);
#pragma unroll
            for (int mf = 0; mf < 4; mf++)
#pragma unroll
                for (int nf = 0; nf < 8; nf++)
                    mma16816(c[mf][nf], ah[mf], &bh[nf >> 1][(nf & 1) * 2]);
        }

        // store wave 1 (stage kt+2 A tile now complete; read 2 barriers later)
        if (pre) sta4(kt + 2, 1, va);
    }

    // ---- epilogue ----
    const int gid = lane >> 2, tig = lane & 3;
#pragma unroll
    for (int mf = 0; mf < 4; mf++) {
#pragma unroll
        for (int nf = 0; nf < 8; nf++) {
            int r0 = mt * BM + wm * 64 + mf * 16 + gid;
            int col = nt * BN + wn * 64 + nf * 8 + tig * 2;
            float* p = out + (size_t)r0 * N_DIM + col;
            *(float2*)p = make_float2(c[mf][nf][0], c[mf][nf][1]);
            *(float2*)(p + 8 * N_DIM) = make_float2(c[mf][nf][2], c[mf][nf][3]);
        }
    }
}

// ---------------------------------------------------------------- launcher
extern "C" void kernel_launch(void* const* d_in, const int* in_sizes, int n_in,
                              void* d_out, int out_size) {
    const float* x      = (const float*)d_in[0];   // (4,2048,1024,4) == A fp32
    const float* weight = (const float*)d_in[1];   // (1024,4)
    const float* ws     = (const float*)d_in[2];   // (1024,1024)
    float* out          = (float*)d_out;           // (4,2048,1024)

    convert_w<<<2048, 256>>>(weight, ws);

    cudaFuncSetAttribute(gemm_mma, cudaFuncAttributeMaxDynamicSharedMemorySize, SMEM_BYTES);
    dim3 grid(N_DIM / BN, M_DIM / BM);   // (8, 64), nt fastest for L2 reuse of A
    gemm_mma<<<grid, 128, SMEM_BYTES>>>(x, out);
}

// round 13
// speedup vs baseline: 1.7319x; 1.7319x over previous
#include <cuda_runtime.h>
#include <cuda_fp16.h>
#include <cstdint>

// out[b,h,o] = sum_{i,d} x[b,h,i,d] * ws[o,i] * weight[o,d]
// => C (8192x1024) = A (8192x4096) . W2^T,  W2[n,k] = ws[n,k>>2]*weight[n,k&3]
// Single-term fp16 HMMA GEMM, R9 champion shape (2x2 warp grid, 64x64 warp
// tiles, BK=32, 4 stages, 2 CTAs/SM). This round: converts merged into one
// launch; cp.async refill hoisted to the top of the iteration.

#define M_DIM 8192
#define N_DIM 1024
#define K_DIM 4096
#define BM 128
#define BN 128
#define BK 32
#define KT (K_DIM / BK)        // 128
#define ROWB 80                // 32 f16 (64B) + 16B pad -> conflict-free ldmatrix
#define TILE_B (128 * ROWB)    // 10240 B per tile
#define STAGE (2 * TILE_B)     // A tile + B tile = 20480 B
#define NSTAGE 4
#define SMEM_BYTES (NSTAGE * STAGE)   // 81920 B -> 2 CTAs/SM

// Precomputed fp16 operands (plain row-major).
__device__ __half g_a[(size_t)M_DIM * K_DIM];
__device__ __half g_b[(size_t)N_DIM * K_DIM];

// ---------------------------------------------------------------- helpers
__device__ __forceinline__ void ldsm_x4(uint32_t* r, uint32_t addr) {
    asm volatile("ldmatrix.sync.aligned.m8n8.x4.shared.b16 {%0,%1,%2,%3}, [%4];"
                 : "=r"(r[0]), "=r"(r[1]), "=r"(r[2]), "=r"(r[3]) : "r"(addr));
}
__device__ __forceinline__ void mma16816(float* c, const uint32_t* a, const uint32_t* b) {
    asm volatile(
        "mma.sync.aligned.m16n8k16.row.col.f32.f16.f16.f32 "
        "{%0,%1,%2,%3}, {%4,%5,%6,%7}, {%8,%9}, {%0,%1,%2,%3};"
        : "+f"(c[0]), "+f"(c[1]), "+f"(c[2]), "+f"(c[3])
        : "r"(a[0]), "r"(a[1]), "r"(a[2]), "r"(a[3]), "r"(b[0]), "r"(b[1]));
}
__device__ __forceinline__ void cp16(uint32_t dst, const void* src) {
    asm volatile("cp.async.cg.shared.global [%0], [%1], 16;"
                 :: "r"(dst), "l"(src) : "memory");
}
__device__ __forceinline__ uint32_t pack_h2(float a, float b) {
    uint32_t r;
    asm volatile("cvt.rn.f16x2.f32 %0, %1, %2;" : "=r"(r) : "f"(b), "f"(a));
    return r;
}

// ------------------------- merged conversion: x -> g_a, (ws,weight) -> g_b
// Blocks [0, 16384): convert 8 fp32 x-elements per thread into g_a.
// Blocks [16384, 18432): build 8 W2 fp16 elements per thread into g_b.
__global__ __launch_bounds__(256) void convert_all(const float* __restrict__ x,
                                                   const float* __restrict__ weight,
                                                   const float* __restrict__ ws) {
    if (blockIdx.x < 16384) {
        size_t idx = (size_t)blockIdx.x * 256 + threadIdx.x;   // 4,194,304 threads
        size_t base = idx * 8;
        float4 t0 = *(const float4*)(x + base);
        float4 t1 = *(const float4*)(x + base + 4);
        uint4 o;
        o.x = pack_h2(t0.x, t0.y);
        o.y = pack_h2(t0.z, t0.w);
        o.z = pack_h2(t1.x, t1.y);
        o.w = pack_h2(t1.z, t1.w);
        *(uint4*)(g_a + base) = o;
    } else {
        size_t idx = (size_t)(blockIdx.x - 16384) * 256 + threadIdx.x;  // 524,288
        int n  = (int)(idx >> 9);
        int kk = ((int)idx & 511) * 8;     // 8 consecutive k = 2 i-values x 4 d
        int i0 = kk >> 2;
        float2 sv = *(const float2*)(ws + (size_t)n * 1024 + i0);
        float4 wv = *(const float4*)(weight + n * 4);
        uint4 o;
        o.x = pack_h2(sv.x * wv.x, sv.x * wv.y);
        o.y = pack_h2(sv.x * wv.z, sv.x * wv.w);
        o.z = pack_h2(sv.y * wv.x, sv.y * wv.y);
        o.w = pack_h2(sv.y * wv.z, sv.y * wv.w);
        *(uint4*)(g_b + (size_t)n * K_DIM + kk) = o;
    }
}

// ----------------------------------------------------------- HMMA GEMM
__global__ __launch_bounds__(128, 2)
void gemm_mma(float* __restrict__ out) {
    extern __shared__ uint8_t smem[];
    uint32_t sbase = (uint32_t)__cvta_generic_to_shared(smem);

    const int tid = threadIdx.x, lane = tid & 31, wid = tid >> 5;
    const int wm = wid >> 1;          // 0..1  (64 rows)
    const int wn = wid & 1;           // 0..1  (64 cols)
    const int nt = blockIdx.x, mt = blockIdx.y;

    float c[4][8][4];
#pragma unroll
    for (int i = 0; i < 4; i++)
#pragma unroll
        for (int j = 0; j < 8; j++)
#pragma unroll
            for (int q = 0; q < 4; q++) c[i][j][q] = 0.0f;

    const __half* asrc = g_a + (size_t)mt * BM * K_DIM;
    const __half* bsrc = g_b + (size_t)nt * BN * K_DIM;

    auto issue = [&](int kt) {
        int k0 = kt * BK;
        uint32_t sst = sbase + (kt % NSTAGE) * STAGE;
#pragma unroll
        for (int it = 0; it < 4; it++) {
            int idx = it * 128 + tid;          // 0..511
            int row = idx >> 2, ch = idx & 3;  // 128 rows x 4 chunks
            cp16(sst + row * ROWB + ch * 16,
                 asrc + (size_t)row * K_DIM + k0 + ch * 8);
        }
#pragma unroll
        for (int it = 0; it < 4; it++) {
            int idx = it * 128 + tid;
            int row = idx >> 2, ch = idx & 3;
            cp16(sst + TILE_B + row * ROWB + ch * 16,
                 bsrc + (size_t)row * K_DIM + k0 + ch * 8);
        }
    };

    // fragment smem addressing (constant per thread)
    const int rA = wm * 64 + (lane & 15);                          // + mf*16
    const uint32_t kAofs = (((uint32_t)lane >> 4) & 1) * 8;        // + ks*16
    const int rB = wn * 64 + (lane & 7) + (((lane >> 4) & 1) * 8); // + nh*16
    const uint32_t kBofs = (((uint32_t)lane >> 3) & 1) * 8;

    // prologue: fill 3 of 4 stages
    issue(0); asm volatile("cp.async.commit_group;" ::: "memory");
    issue(1); asm volatile("cp.async.commit_group;" ::: "memory");
    issue(2); asm volatile("cp.async.commit_group;" ::: "memory");

    for (int kt = 0; kt < KT; kt++) {
        asm volatile("cp.async.wait_group 2;" ::: "memory");
        __syncthreads();

        // refill stage (kt+3)%4 == (kt-1)%4 immediately (safe post-barrier);
        // the DRAM fetch runs under this iteration's ldsm+mma work.
        if (kt + 3 < KT) issue(kt + 3);
        asm volatile("cp.async.commit_group;" ::: "memory");

        uint32_t sA = sbase + (kt % NSTAGE) * STAGE;
        uint32_t sB = sA + TILE_B;

#pragma unroll
        for (int ks = 0; ks < 2; ks++) {
            uint32_t ka = (ks * 16 + kAofs) * 2;
            uint32_t kb = (ks * 16 + kBofs) * 2;
            uint32_t ah[4][4], bh[4][4];
#pragma unroll
            for (int nh = 0; nh < 4; nh++)
                ldsm_x4(bh[nh], sB + (uint32_t)(rB + nh * 16) * ROWB + kb);
#pragma unroll
            for (int mf = 0; mf < 4; mf++)
                ldsm_x4(ah[mf], sA + (uint32_t)(rA + mf * 16) * ROWB + ka);

#pragma unroll
            for (int mf = 0; mf < 4; mf++)
#pragma unroll
                for (int nf = 0; nf < 8; nf++)
                    mma16816(c[mf][nf], ah[mf], &bh[nf >> 1][(nf & 1) * 2]);
        }
    }

    // ---- epilogue ----
    const int gid = lane >> 2, tig = lane & 3;
#pragma unroll
    for (int mf = 0; mf < 4; mf++) {
#pragma unroll
        for (int nf = 0; nf < 8; nf++) {
            int r0 = mt * BM + wm * 64 + mf * 16 + gid;
            int col = nt * BN + wn * 64 + nf * 8 + tig * 2;
            float* p = out + (size_t)r0 * N_DIM + col;
            *(float2*)p = make_float2(c[mf][nf][0], c[mf][nf][1]);
            *(float2*)(p + 8 * N_DIM) = make_float2(c[mf][nf][2], c[mf][nf][3]);
        }
    }
}

// ---------------------------------------------------------------- launcher
extern "C" void kernel_launch(void* const* d_in, const int* in_sizes, int n_in,
                              void* d_out, int out_size) {
    const float* x      = (const float*)d_in[0];   // (4,2048,1024,4)
    const float* weight = (const float*)d_in[1];   // (1024,4)
    const float* ws     = (const float*)d_in[2];   // (1024,1024)
    float* out          = (float*)d_out;           // (4,2048,1024)

    convert_all<<<16384 + 2048, 256>>>(x, weight, ws);

    cudaFuncSetAttribute(gemm_mma, cudaFuncAttributeMaxDynamicSharedMemorySize, SMEM_BYTES);
    dim3 grid(N_DIM / BN, M_DIM / BM);   // (8, 64), nt fastest for L2 reuse of A
    gemm_mma<<<grid, 128, SMEM_BYTES>>>(out);
}

// round 14
// speedup vs baseline: 1.8764x; 1.0834x over previous
#include <cuda_runtime.h>
#include <cuda_fp16.h>
#include <cstdint>

// out[b,h,o] = sum_{i,d} x[b,h,i,d] * ws[o,i] * weight[o,d]
// => C (8192x1024) = A (8192x4096) . W2^T,  W2[n,k] = ws[n,k>>2]*weight[n,k&3]
// Single-term fp16 HMMA GEMM, R9 champion shape (2x2 warp grid, 64x64 warp
// tiles, BK=32, 4 stages, 2 CTAs/SM), refill at loop bottom (proven ordering),
// plus the single merged conversion launch.

#define M_DIM 8192
#define N_DIM 1024
#define K_DIM 4096
#define BM 128
#define BN 128
#define BK 32
#define KT (K_DIM / BK)        // 128
#define ROWB 80                // 32 f16 (64B) + 16B pad -> conflict-free ldmatrix
#define TILE_B (128 * ROWB)    // 10240 B per tile
#define STAGE (2 * TILE_B)     // A tile + B tile = 20480 B
#define NSTAGE 4
#define SMEM_BYTES (NSTAGE * STAGE)   // 81920 B -> 2 CTAs/SM

// Precomputed fp16 operands (plain row-major).
__device__ __half g_a[(size_t)M_DIM * K_DIM];
__device__ __half g_b[(size_t)N_DIM * K_DIM];

// ---------------------------------------------------------------- helpers
__device__ __forceinline__ void ldsm_x4(uint32_t* r, uint32_t addr) {
    asm volatile("ldmatrix.sync.aligned.m8n8.x4.shared.b16 {%0,%1,%2,%3}, [%4];"
                 : "=r"(r[0]), "=r"(r[1]), "=r"(r[2]), "=r"(r[3]) : "r"(addr));
}
__device__ __forceinline__ void mma16816(float* c, const uint32_t* a, const uint32_t* b) {
    asm volatile(
        "mma.sync.aligned.m16n8k16.row.col.f32.f16.f16.f32 "
        "{%0,%1,%2,%3}, {%4,%5,%6,%7}, {%8,%9}, {%0,%1,%2,%3};"
        : "+f"(c[0]), "+f"(c[1]), "+f"(c[2]), "+f"(c[3])
        : "r"(a[0]), "r"(a[1]), "r"(a[2]), "r"(a[3]), "r"(b[0]), "r"(b[1]));
}
__device__ __forceinline__ void cp16(uint32_t dst, const void* src) {
    asm volatile("cp.async.cg.shared.global [%0], [%1], 16;"
                 :: "r"(dst), "l"(src) : "memory");
}
__device__ __forceinline__ uint32_t pack_h2(float a, float b) {
    uint32_t r;
    asm volatile("cvt.rn.f16x2.f32 %0, %1, %2;" : "=r"(r) : "f"(b), "f"(a));
    return r;
}

// ------------------------- merged conversion: x -> g_a, (ws,weight) -> g_b
__global__ __launch_bounds__(256) void convert_all(const float* __restrict__ x,
                                                   const float* __restrict__ weight,
                                                   const float* __restrict__ ws) {
    if (blockIdx.x < 16384) {
        size_t idx = (size_t)blockIdx.x * 256 + threadIdx.x;   // 4,194,304 threads
        size_t base = idx * 8;
        float4 t0 = *(const float4*)(x + base);
        float4 t1 = *(const float4*)(x + base + 4);
        uint4 o;
        o.x = pack_h2(t0.x, t0.y);
        o.y = pack_h2(t0.z, t0.w);
        o.z = pack_h2(t1.x, t1.y);
        o.w = pack_h2(t1.z, t1.w);
        *(uint4*)(g_a + base) = o;
    } else {
        size_t idx = (size_t)(blockIdx.x - 16384) * 256 + threadIdx.x;  // 524,288
        int n  = (int)(idx >> 9);
        int kk = ((int)idx & 511) * 8;     // 8 consecutive k = 2 i-values x 4 d
        int i0 = kk >> 2;
        float2 sv = *(const float2*)(ws + (size_t)n * 1024 + i0);
        float4 wv = *(const float4*)(weight + n * 4);
        uint4 o;
        o.x = pack_h2(sv.x * wv.x, sv.x * wv.y);
        o.y = pack_h2(sv.x * wv.z, sv.x * wv.w);
        o.z = pack_h2(sv.y * wv.x, sv.y * wv.y);
        o.w = pack_h2(sv.y * wv.z, sv.y * wv.w);
        *(uint4*)(g_b + (size_t)n * K_DIM + kk) = o;
    }
}

// ----------------------------------------------------------- HMMA GEMM
__global__ __launch_bounds__(128, 2)
void gemm_mma(float* __restrict__ out) {
    extern __shared__ uint8_t smem[];
    uint32_t sbase = (uint32_t)__cvta_generic_to_shared(smem);

    const int tid = threadIdx.x, lane = tid & 31, wid = tid >> 5;
    const int wm = wid >> 1;          // 0..1  (64 rows)
    const int wn = wid & 1;           // 0..1  (64 cols)
    const int nt = blockIdx.x, mt = blockIdx.y;

    float c[4][8][4];
#pragma unroll
    for (int i = 0; i < 4; i++)
#pragma unroll
        for (int j = 0; j < 8; j++)
#pragma unroll
            for (int q = 0; q < 4; q++) c[i][j][q] = 0.0f;

    const __half* asrc = g_a + (size_t)mt * BM * K_DIM;
    const __half* bsrc = g_b + (size_t)nt * BN * K_DIM;

    auto issue = [&](int kt) {
        int k0 = kt * BK;
        uint32_t sst = sbase + (kt % NSTAGE) * STAGE;
#pragma unroll
        for (int it = 0; it < 4; it++) {
            int idx = it * 128 + tid;          // 0..511
            int row = idx >> 2, ch = idx & 3;  // 128 rows x 4 chunks
            cp16(sst + row * ROWB + ch * 16,
                 asrc + (size_t)row * K_DIM + k0 + ch * 8);
        }
#pragma unroll
        for (int it = 0; it < 4; it++) {
            int idx = it * 128 + tid;
            int row = idx >> 2, ch = idx & 3;
            cp16(sst + TILE_B + row * ROWB + ch * 16,
                 bsrc + (size_t)row * K_DIM + k0 + ch * 8);
        }
    };

    // fragment smem addressing (constant per thread)
    const int rA = wm * 64 + (lane & 15);                          // + mf*16
    const uint32_t kAofs = (((uint32_t)lane >> 4) & 1) * 8;        // + ks*16
    const int rB = wn * 64 + (lane & 7) + (((lane >> 4) & 1) * 8); // + nh*16
    const uint32_t kBofs = (((uint32_t)lane >> 3) & 1) * 8;

    // prologue: fill 3 of 4 stages
    issue(0); asm volatile("cp.async.commit_group;" ::: "memory");
    issue(1); asm volatile("cp.async.commit_group;" ::: "memory");
    issue(2); asm volatile("cp.async.commit_group;" ::: "memory");

    for (int kt = 0; kt < KT; kt++) {
        asm volatile("cp.async.wait_group 2;" ::: "memory");
        __syncthreads();

        uint32_t sA = sbase + (kt % NSTAGE) * STAGE;
        uint32_t sB = sA + TILE_B;

#pragma unroll
        for (int ks = 0; ks < 2; ks++) {
            uint32_t ka = (ks * 16 + kAofs) * 2;
            uint32_t kb = (ks * 16 + kBofs) * 2;
            uint32_t ah[4][4], bh[4][4];
#pragma unroll
            for (int nh = 0; nh < 4; nh++)
                ldsm_x4(bh[nh], sB + (uint32_t)(rB + nh * 16) * ROWB + kb);
#pragma unroll
            for (int mf = 0; mf < 4; mf++)
                ldsm_x4(ah[mf], sA + (uint32_t)(rA + mf * 16) * ROWB + ka);

#pragma unroll
            for (int mf = 0; mf < 4; mf++)
#pragma unroll
                for (int nf = 0; nf < 8; nf++)
                    mma16816(c[mf][nf], ah[mf], &bh[nf >> 1][(nf & 1) * 2]);
        }

        // refill at loop bottom -- the proven R9 ordering (cp.async fills
        // idle LSU slots after the mma block instead of delaying the ldsm).
        if (kt + 3 < KT) issue(kt + 3);
        asm volatile("cp.async.commit_group;" ::: "memory");
    }

    // ---- epilogue ----
    const int gid = lane >> 2, tig = lane & 3;
#pragma unroll
    for (int mf = 0; mf < 4; mf++) {
#pragma unroll
        for (int nf = 0; nf < 8; nf++) {
            int r0 = mt * BM + wm * 64 + mf * 16 + gid;
            int col = nt * BN + wn * 64 + nf * 8 + tig * 2;
            float* p = out + (size_t)r0 * N_DIM + col;
            *(float2*)p = make_float2(c[mf][nf][0], c[mf][nf][1]);
            *(float2*)(p + 8 * N_DIM) = make_float2(c[mf][nf][2], c[mf][nf][3]);
        }
    }
}

// ---------------------------------------------------------------- launcher
extern "C" void kernel_launch(void* const* d_in, const int* in_sizes, int n_in,
                              void* d_out, int out_size) {
    const float* x      = (const float*)d_in[0];   // (4,2048,1024,4)
    const float* weight = (const float*)d_in[1];   // (1024,4)
    const float* ws     = (const float*)d_in[2];   // (1024,1024)
    float* out          = (float*)d_out;           // (4,2048,1024)

    convert_all<<<16384 + 2048, 256>>>(x, weight, ws);

    cudaFuncSetAttribute(gemm_mma, cudaFuncAttributeMaxDynamicSharedMemorySize, SMEM_BYTES);
    dim3 grid(N_DIM / BN, M_DIM / BM);   // (8, 64), nt fastest for L2 reuse of A
    gemm_mma<<<grid, 128, SMEM_BYTES>>>(out);
}